// round 11
// baseline (speedup 1.0000x reference)
#include <cuda_runtime.h>
#include <cuda_bf16.h>

// GraphGather / segment_sum, atomic-free + zero-pass-free:
//   out[b, :] = sum of feats[a, :] for membership[a] == b
// feats: [524288, 128] f32, membership: [524288] i32 (SORTED), out: [16384, 128] f32.
//
// R11: two kernels, no atomics, no output pre-zeroing.
//  Kernel A (prepass, ~0.8us): materialize starts[s] = lower_bound(memb, s)
//    for s in [0, batch]. Thread per row; boundary threads write, last thread
//    fills the tail (handles empty segments too). Rewrites fully every run.
//  Kernel B: warp-per-segment. Range via two cached scalar loads from
//    starts[] (no binary search). Rows streamed in 8-deep PREDICATED float4
//    batches (front-batched -> MLP 8; masked-off loads issue no traffic).
//    Exactly one plain STG.128 per lane per output row; empty segments
//    naturally store zeros -> poisoned output fully overwritten.

#define N_FEAT 128
#define FEAT4 (N_FEAT / 4)       // 32 float4 per row
#define TPB 256
#define MAX_BATCH 16512

__device__ int g_starts[MAX_BATCH + 1];

__global__ __launch_bounds__(TPB)
void gg_starts_kernel(const int* __restrict__ memb, int n_atoms, int batch) {
    int r = blockIdx.x * blockDim.x + threadIdx.x;
    if (r >= n_atoms) return;
    int m = memb[r];
    int prev = (r == 0) ? -1 : memb[r - 1];
    // Boundary rows write the start index for every segment beginning here
    // (covers runs of empty segments as well).
    for (int s = prev + 1; s <= m; ++s)
        g_starts[s] = r;
    if (r == n_atoms - 1) {
        for (int s = m + 1; s <= batch; ++s)
            g_starts[s] = n_atoms;
    }
}

__global__ __launch_bounds__(TPB)
void gg_segsum_kernel(const float4* __restrict__ feats,
                      float4* __restrict__ out,
                      int batch) {
    const int seg = (blockIdx.x * TPB + threadIdx.x) >> 5;   // warp id = segment
    const int lane = threadIdx.x & 31;
    if (seg >= batch) return;

    // Warp-uniform range (L1/L2-hot 64KB array).
    const int start = g_starts[seg];
    const int len = g_starts[seg + 1] - start;

    const float4* base = feats + (size_t)start * FEAT4 + lane;
    float4 acc = make_float4(0.f, 0.f, 0.f, 0.f);
    const float4 z = make_float4(0.f, 0.f, 0.f, 0.f);

    // 8-deep predicated batches: loads front-batched (MLP_p1 = 8),
    // masked-off lanes generate no memory traffic.
    for (int bt = 0; bt * 8 < len; ++bt) {
        float4 v[8];
        #pragma unroll
        for (int i = 0; i < 8; ++i) {
            int r = bt * 8 + i;
            v[i] = (r < len) ? __ldcs(base + (size_t)r * FEAT4) : z;
        }
        #pragma unroll
        for (int i = 0; i < 8; ++i) {
            acc.x += v[i].x; acc.y += v[i].y;
            acc.z += v[i].z; acc.w += v[i].w;
        }
    }

    // One plain coalesced store per lane; empty segments write zeros.
    out[(size_t)seg * FEAT4 + lane] = acc;
}

extern "C" void kernel_launch(void* const* d_in, const int* in_sizes, int n_in,
                              void* d_out, int out_size) {
    const float* feats = (const float*)d_in[0];
    const int* memb = (const int*)d_in[1];
    float* out = (float*)d_out;

    const int n_atoms = in_sizes[1];          // 524288
    int batch = out_size / N_FEAT;            // 16384
    if (batch > MAX_BATCH) batch = MAX_BATCH; // fixed-shape safety

    // Prepass: segment start offsets.
    gg_starts_kernel<<<(n_atoms + TPB - 1) / TPB, TPB>>>(memb, n_atoms, batch);

    // Main: warp per segment, plain stores, no init needed.
    const int n_warps = batch;
    const int blocks = (n_warps + (TPB / 32) - 1) / (TPB / 32);
    gg_segsum_kernel<<<blocks, TPB>>>((const float4*)feats, (float4*)out, batch);
}